// round 1
// baseline (speedup 1.0000x reference)
#include <cuda_runtime.h>

#define N_SUBDOCS 4096
#define N_WORDS   128
#define DIM       768
#define N_DOCS    256

// scratch for per-subdoc pooled logits (allocation-free per harness rules)
__device__ float g_zpool[N_SUBDOCS];

// Kernel 1: per-subdoc word softmax-pool.
// One CTA per subdoc, 512 threads (16 warps). Each warp handles 8 words.
// W kept in registers (same lane-strided layout as the embedding loads).
__global__ __launch_bounds__(512) void pool_words_kernel(
    const float* __restrict__ emb,   // [N_SUBDOCS, N_WORDS, DIM]
    const float* __restrict__ W,     // [DIM]
    const float* __restrict__ b,     // [1]
    const float* __restrict__ logt,  // [1]
    float* __restrict__ zpool)       // [N_SUBDOCS]
{
    __shared__ float sz[N_WORDS];

    const int tid  = threadIdx.x;
    const int lane = tid & 31;
    const int warp = tid >> 5;

    // Load W into registers: lane i holds W4[i], W4[i+32], ..., W4[i+160]
    float4 wreg[6];
    const float4* W4 = reinterpret_cast<const float4*>(W);
    #pragma unroll
    for (int i = 0; i < 6; i++) wreg[i] = W4[lane + i * 32];
    const float bias = b[0];

    const float* base = emb + (size_t)blockIdx.x * (N_WORDS * DIM);

    #pragma unroll
    for (int w = warp; w < N_WORDS; w += 16) {
        const float4* row = reinterpret_cast<const float4*>(base + w * DIM);
        float acc = 0.f;
        #pragma unroll
        for (int i = 0; i < 6; i++) {
            float4 e = row[lane + i * 32];
            acc += e.x * wreg[i].x + e.y * wreg[i].y
                 + e.z * wreg[i].z + e.w * wreg[i].w;
        }
        // warp-wide sum reduction
        #pragma unroll
        for (int o = 16; o; o >>= 1) acc += __shfl_xor_sync(0xffffffffu, acc, o);
        if (lane == 0) sz[w] = acc + bias;
    }
    __syncthreads();

    // Warp 0: softmax-pool over the 128 word logits:
    //   sum(z * softmax(t*z))  (max-stabilized; stabilization cancels exactly)
    if (warp == 0) {
        const float t = expf(logt[0]);
        float v[4];
        float m = -1e30f;
        #pragma unroll
        for (int i = 0; i < 4; i++) {
            v[i] = sz[lane + 32 * i];
            m = fmaxf(m, t * v[i]);
        }
        #pragma unroll
        for (int o = 16; o; o >>= 1)
            m = fmaxf(m, __shfl_xor_sync(0xffffffffu, m, o));
        float se = 0.f, sn = 0.f;
        #pragma unroll
        for (int i = 0; i < 4; i++) {
            float e = expf(t * v[i] - m);
            se += e;
            sn += v[i] * e;
        }
        #pragma unroll
        for (int o = 16; o; o >>= 1) {
            se += __shfl_xor_sync(0xffffffffu, se, o);
            sn += __shfl_xor_sync(0xffffffffu, sn, o);
        }
        if (lane == 0) zpool[blockIdx.x] = sn / se;
    }
}

// Kernel 2: ragged segment softmax-pool over subdocs + sigmoid.
// Single CTA, one thread per document. Lengths scanned in shared memory.
__global__ __launch_bounds__(N_DOCS) void pool_docs_kernel(
    const float* __restrict__ zpool,  // [N_SUBDOCS]
    const int* __restrict__ lens,     // [N_DOCS]
    const float* __restrict__ logt,   // [1]
    float* __restrict__ out)          // [N_DOCS]
{
    __shared__ int scan[N_DOCS];
    const int tid = threadIdx.x;
    const int len = lens[tid];
    scan[tid] = len;
    __syncthreads();

    // Hillis-Steele inclusive scan
    for (int d = 1; d < N_DOCS; d <<= 1) {
        int v = (tid >= d) ? scan[tid - d] : 0;
        __syncthreads();
        scan[tid] += v;
        __syncthreads();
    }

    const int end   = scan[tid];
    const int start = end - len;
    const float t   = expf(logt[0]);

    float m = -1e30f;
    for (int i = start; i < end; i++) m = fmaxf(m, t * zpool[i]);

    float se = 0.f, sn = 0.f;
    for (int i = start; i < end; i++) {
        float z = zpool[i];
        float e = expf(t * z - m);
        se += e;
        sn += z * e;
    }
    float zp = sn / se;
    out[tid] = 1.f / (1.f + expf(-zp));
}

extern "C" void kernel_launch(void* const* d_in, const int* in_sizes, int n_in,
                              void* d_out, int out_size) {
    const float* emb  = (const float*)d_in[0];  // embeddings [4096,128,768] f32
    const float* W    = (const float*)d_in[1];  // [1,768] f32
    const float* b    = (const float*)d_in[2];  // [1] f32
    const float* logt = (const float*)d_in[3];  // [1] f32
    const int*   lens = (const int*)d_in[4];    // [256] i32
    float* out = (float*)d_out;                 // [256] f32

    float* zpool = nullptr;
    cudaGetSymbolAddress((void**)&zpool, g_zpool);

    pool_words_kernel<<<N_SUBDOCS, 512>>>(emb, W, b, logt, zpool);
    pool_docs_kernel<<<1, N_DOCS>>>(zpool, lens, logt, out);
}